// round 15
// baseline (speedup 1.0000x reference)
#include <cuda_runtime.h>
#include <cuda_bf16.h>
#include <cstdint>

#define D_OUT_ 32768
#define D_IN_  1024

// Scratch (device globals: allocation-free rule)
static __device__ __nv_bfloat16 g_dw[(size_t)D_OUT_ * D_IN_];   // 64 MB bf16(DeltaW)
static __device__ __nv_bfloat16 g_sig[(size_t)D_IN_ * D_IN_];   // 2 MB bf16(Sigma)
static __device__ float  g_g[D_OUT_];                            // per-row g accum
static __device__ float  g_br[1024];                             // per-CTA binary-reg partials
static __device__ double g_acc[3];  // 0: act, 1: binary reg, 2: sum g^2
static __device__ int    g_tick;    // sq last-block ticket

// ---------------- PTX helpers (baseline PTX only; no sm_103a features) -----
__device__ __forceinline__ uint32_t smem_u32(const void* p) {
    uint32_t a;
    asm("{ .reg .u64 t; cvta.to.shared.u64 t, %1; cvt.u32.u64 %0, t; }" : "=r"(a) : "l"(p));
    return a;
}
#define CPA16(dst, src) \
    asm volatile("cp.async.cg.shared.global [%0], [%1], 16;" :: "r"(dst), "l"(src))
#define CPCOMMIT() asm volatile("cp.async.commit_group;" ::: "memory")
#define CPWAIT(n)  asm volatile("cp.async.wait_group %0;" :: "n"(n) : "memory")

#define LDSM4(r0, r1, r2, r3, a) \
    asm volatile("ldmatrix.sync.aligned.m8n8.x4.shared.b16 {%0,%1,%2,%3}, [%4];" \
        : "=r"(r0), "=r"(r1), "=r"(r2), "=r"(r3) : "r"(a))

#define MMA16816(c0, c1, c2, c3, a0, a1, a2, a3, b0, b1) \
    asm volatile("mma.sync.aligned.m16n8k16.row.col.f32.bf16.bf16.f32 " \
        "{%0,%1,%2,%3}, {%4,%5,%6,%7}, {%8,%9}, {%0,%1,%2,%3};" \
        : "+f"(c0), "+f"(c1), "+f"(c2), "+f"(c3) \
        : "r"(a0), "r"(a1), "r"(a2), "r"(a3), "r"(b0), "r"(b1))

#define SWZ(o) ((o) ^ (((o) >> 3) & 0x70))

__device__ __forceinline__ float2 bf2f2(uint32_t v) {
    __nv_bfloat162 b;
    *reinterpret_cast<uint32_t*>(&b) = v;
    return __bfloat1622float2(b);
}
__device__ __forceinline__ float tanha(float x) {
    float y;
    asm("tanh.approx.f32 %0, %1;" : "=f"(y) : "f"(x));
    return y;
}

// ---------------- kernels --------------------------------------------------

// Prologue: zero accumulators (safe: gemm/sq run after prep in stream order).
// Then Sigma->bf16, then Th/DW (2-way interleaved). Binary-reg partial goes to
// g_br[blockIdx] (plain store; no dependence on g_acc zeroing order).
__global__ void prep_kernel(const float4* __restrict__ W, const float4* __restrict__ Q,
                            const float* __restrict__ s, const float4* __restrict__ T,
                            const float4* __restrict__ S) {
    const int gtid = blockIdx.x * blockDim.x + threadIdx.x;
    const int gstr = gridDim.x * blockDim.x;

    // zero g_g / g_acc / ticket (consumed only by later kernels)
    for (int i = gtid; i < D_OUT_; i += gstr) g_g[i] = 0.f;
    if (gtid == 0) { g_acc[0] = 0.0; g_acc[1] = 0.0; g_acc[2] = 0.0; g_tick = 0; }

    // Sigma convert: 1024*1024/4 = 262144 float4
    {
        uint2* outs = reinterpret_cast<uint2*>(g_sig);
        for (int i = gtid; i < D_IN_ * D_IN_ / 4; i += gstr) {
            float4 v = S[i];
            __nv_bfloat162 p0, p1;
            p0.x = __float2bfloat16_rn(v.x); p0.y = __float2bfloat16_rn(v.y);
            p1.x = __float2bfloat16_rn(v.z); p1.y = __float2bfloat16_rn(v.w);
            uint2 u;
            u.x = *reinterpret_cast<uint32_t*>(&p0);
            u.y = *reinterpret_cast<uint32_t*>(&p1);
            outs[i] = u;
        }
    }

    const int n4 = D_OUT_ * D_IN_ / 4;
    const int half = n4 >> 1;
    float br = 0.f;
    uint2* out = reinterpret_cast<uint2*>(g_dw);

    for (int i = gtid; i < half; i += gstr) {
        const int i2 = i + half;
        const float sva = s[i >> 8];
        const float svb = s[i2 >> 8];
        const float4 wa = W[i],  qa = Q[i],  ta = T[i];
        const float4 wb = W[i2], qb = Q[i2], tb = T[i2];

        float tha0 = __saturatef(fmaf(tanha(ta.x), 0.6f, 0.5f));
        float tha1 = __saturatef(fmaf(tanha(ta.y), 0.6f, 0.5f));
        float tha2 = __saturatef(fmaf(tanha(ta.z), 0.6f, 0.5f));
        float tha3 = __saturatef(fmaf(tanha(ta.w), 0.6f, 0.5f));
        float thb0 = __saturatef(fmaf(tanha(tb.x), 0.6f, 0.5f));
        float thb1 = __saturatef(fmaf(tanha(tb.y), 0.6f, 0.5f));
        float thb2 = __saturatef(fmaf(tanha(tb.z), 0.6f, 0.5f));
        float thb3 = __saturatef(fmaf(tanha(tb.w), 0.6f, 0.5f));

        float da0 = wa.x - sva * (qa.x + tha0);
        float da1 = wa.y - sva * (qa.y + tha1);
        float da2 = wa.z - sva * (qa.z + tha2);
        float da3 = wa.w - sva * (qa.w + tha3);
        float db0 = wb.x - svb * (qb.x + thb0);
        float db1 = wb.y - svb * (qb.y + thb1);
        float db2 = wb.z - svb * (qb.z + thb2);
        float db3 = wb.w - svb * (qb.w + thb3);

        float xa0 = 2.f * tha0 - 1.f, xa1 = 2.f * tha1 - 1.f;
        float xa2 = 2.f * tha2 - 1.f, xa3 = 2.f * tha3 - 1.f;
        float xb0 = 2.f * thb0 - 1.f, xb1 = 2.f * thb1 - 1.f;
        float xb2 = 2.f * thb2 - 1.f, xb3 = 2.f * thb3 - 1.f;
        br += (1.f - xa0 * xa0) + (1.f - xa1 * xa1) + (1.f - xa2 * xa2) + (1.f - xa3 * xa3);
        br += (1.f - xb0 * xb0) + (1.f - xb1 * xb1) + (1.f - xb2 * xb2) + (1.f - xb3 * xb3);

        __nv_bfloat162 p0, p1;
        uint2 u;
        p0.x = __float2bfloat16_rn(da0); p0.y = __float2bfloat16_rn(da1);
        p1.x = __float2bfloat16_rn(da2); p1.y = __float2bfloat16_rn(da3);
        u.x = *reinterpret_cast<uint32_t*>(&p0);
        u.y = *reinterpret_cast<uint32_t*>(&p1);
        out[i] = u;
        p0.x = __float2bfloat16_rn(db0); p0.y = __float2bfloat16_rn(db1);
        p1.x = __float2bfloat16_rn(db2); p1.y = __float2bfloat16_rn(db3);
        u.x = *reinterpret_cast<uint32_t*>(&p0);
        u.y = *reinterpret_cast<uint32_t*>(&p1);
        out[i2] = u;
    }
    #pragma unroll
    for (int o = 16; o; o >>= 1) br += __shfl_down_sync(0xFFFFFFFFu, br, o);
    __shared__ float red[8];
    if ((threadIdx.x & 31) == 0) red[threadIdx.x >> 5] = br;
    __syncthreads();
    if (threadIdx.x == 0) {
        float t = 0.f;
        #pragma unroll
        for (int j = 0; j < 8; j++) t += red[j];
        g_br[blockIdx.x] = t;   // plain store, summed by sq_kernel
    }
}

// Persistent streaming GEMM: Z = DW @ Sigma^T.  (R8/R12 structure — validated)
// 2048 units = 256 M-tiles x 8 N-chunks (unit 128x128, full K). 296 CTAs, 2/SM.
// K-chunks stream through a 3-stage cp.async rotation ACROSS unit boundaries.
// 8 warps as 4(M) x 2(N), warp tile 32x64. Fused warp-independent epilogue.
#define NCTAS 296
#define STAGE_BYTES 32768             // 16 KB A + 16 KB B per stage
#define SMEM_BYTES  98304             // 3 stages

__global__ void __launch_bounds__(256, 2) gemm_kernel(const float* __restrict__ Wf) {
    extern __shared__ char smem[];
    const uint32_t s0 = smem_u32(smem);

    const int tid = threadIdx.x;
    const int lane = tid & 31, w = tid >> 5;
    const int wm = w & 3, wn = w >> 2;          // 4 warps along M, 2 along N
    const int grp = lane >> 2, qd = lane & 3;

    // --- work assignment: CTAs 0..271 get 7 units, 272..295 get 6 ---
    const int c = blockIdx.x;
    const int ucount = (c < 272) ? 7 : 6;
    const int ustart = (c < 272) ? 7 * c : 1904 + 6 * (c - 272);
    const int nch = ucount * 16;

    // cp.async coords (A and B tiles both 128 rows x 8 cols of 16B)
    const int ldc = tid & 7;
    const int lr0 = tid >> 3;
    const uint32_t swo[4] = {
        (uint32_t)SWZ((lr0 +  0) * 128 + ldc * 16), (uint32_t)SWZ((lr0 + 32) * 128 + ldc * 16),
        (uint32_t)SWZ((lr0 + 64) * 128 + ldc * 16), (uint32_t)SWZ((lr0 + 96) * 128 + ldc * 16) };

    // ldmatrix bases
    const int arow = wm * 32 + (lane & 7) + ((lane >> 3) & 1) * 8;  // + mt*16
    const int akh  = (lane >> 4) & 1;
    const int asx  = (arow & 7);
    const int bnrow = wn * 64 + (lane & 7) + ((lane >> 4) & 1) * 8; // + nt*16
    const int bkh  = (lane >> 3) & 1;

    float act = 0.f;

    auto load_chunk = [&](int ci) {
        const int u  = ustart + (ci >> 4);
        const int kc = ci & 15;
        const __nv_bfloat16* sa = g_dw  + (size_t)((u >> 3) << 7) * D_IN_ + kc * 64;
        const __nv_bfloat16* sb = g_sig + (size_t)((u & 7)  << 7) * D_IN_ + kc * 64;
        const uint32_t dA = s0 + (ci % 3) * STAGE_BYTES;
        const uint32_t dB = dA + 16384;
        #pragma unroll
        for (int i = 0; i < 4; i++) {
            const int r = lr0 + i * 32;
            CPA16(dA + swo[i], sa + r * D_IN_ + ldc * 8);
            CPA16(dB + swo[i], sb + r * D_IN_ + ldc * 8);
        }
        CPCOMMIT();
    };

    load_chunk(0);
    load_chunk(1);

    int ch = 0;
    #pragma unroll 1
    for (int j = 0; j < ucount; j++) {
        const int u  = ustart + j;
        const int m0 = (u >> 3) << 7;
        const int n0 = (u & 7)  << 7;

        float acc[2][8][4];
        #pragma unroll
        for (int mt = 0; mt < 2; mt++)
            #pragma unroll
            for (int nt = 0; nt < 8; nt++)
                #pragma unroll
                for (int jj = 0; jj < 4; jj++) acc[mt][nt][jj] = 0.f;

        #pragma unroll 1
        for (int kc = 0; kc < 16; kc++, ch++) {
            CPWAIT(1);
            __syncthreads();

            if (ch + 2 < nch) load_chunk(ch + 2);
            else              CPCOMMIT();

            const uint32_t bA = s0 + (ch % 3) * STAGE_BYTES;
            const uint32_t bB = bA + 16384;

            #pragma unroll
            for (int ks = 0; ks < 4; ks++) {
                uint32_t a[2][4], b[8][2];
                #pragma unroll
                for (int mt = 0; mt < 2; mt++) {
                    uint32_t addr = bA + (arow + mt * 16) * 128 +
                                    (((ks * 2 + akh) ^ asx) * 16);
                    LDSM4(a[mt][0], a[mt][1], a[mt][2], a[mt][3], addr);
                }
                #pragma unroll
                for (int np = 0; np < 4; np++) {
                    const int n = bnrow + np * 16;
                    uint32_t addr = bB + n * 128 + (((ks * 2 + bkh) ^ (n & 7)) * 16);
                    LDSM4(b[2 * np][0], b[2 * np][1], b[2 * np + 1][0], b[2 * np + 1][1], addr);
                }
                #pragma unroll
                for (int mt = 0; mt < 2; mt++)
                    #pragma unroll
                    for (int nt = 0; nt < 8; nt++)
                        MMA16816(acc[mt][nt][0], acc[mt][nt][1], acc[mt][nt][2], acc[mt][nt][3],
                                 a[mt][0], a[mt][1], a[mt][2], a[mt][3],
                                 b[nt][0], b[nt][1]);
            }
        }

        // ---- fused warp-independent epilogue ----
        #pragma unroll
        for (int mt = 0; mt < 2; mt++) {
            #pragma unroll
            for (int half = 0; half < 2; half++) {
                const int row = m0 + wm * 32 + mt * 16 + grp + half * 8;
                const float*         wrow = Wf   + (size_t)row * D_IN_ + n0 + wn * 64;
                const __nv_bfloat16* drow = g_dw + (size_t)row * D_IN_ + n0 + wn * 64;
                float ga = 0.f;
                #pragma unroll
                for (int nt = 0; nt < 8; nt++) {
                    const int col = nt * 8 + qd * 2;
                    float z0 = acc[mt][nt][half * 2 + 0];
                    float z1 = acc[mt][nt][half * 2 + 1];
                    float2 dv = bf2f2(*(const uint32_t*)(drow + col));
                    float2 wv = *(const float2*)(wrow + col);
                    act = fmaf(z0, dv.x, act); act = fmaf(z1, dv.y, act);
                    ga  = fmaf(z0, wv.x, ga);  ga  = fmaf(z1, wv.y, ga);
                }
                ga += __shfl_xor_sync(0xFFFFFFFFu, ga, 1);
                ga += __shfl_xor_sync(0xFFFFFFFFu, ga, 2);
                if (qd == 0) atomicAdd(&g_g[row], ga);
            }
        }
        // next unit's first CPWAIT + __syncthreads orders stage reuse
    }

    // CTA reduce act -> double atomic
    #pragma unroll
    for (int o = 16; o; o >>= 1) act += __shfl_down_sync(0xFFFFFFFFu, act, o);
    __shared__ float reda[8];
    if (lane == 0) reda[w] = act;
    __syncthreads();
    if (tid == 0) {
        float t = 0.f;
        #pragma unroll
        for (int jj = 0; jj < 8; jj++) t += reda[jj];
        atomicAdd(&g_acc[0], (double)t);
    }
}

// sum g^2 + binary-reg partials; last block (ticket) writes the final output
__global__ void sq_kernel(float* __restrict__ out) {
    const int t = threadIdx.x;
    const int b = blockIdx.x;
    const int gtid = b * 256 + t;

    double sg = 0.0;
    for (int i = gtid; i < D_OUT_; i += 64 * 256) {
        double v = (double)g_g[i];
        sg += v * v;
    }
    double br = (t < 16) ? (double)g_br[b * 16 + t] : 0.0;

    #pragma unroll
    for (int o = 16; o; o >>= 1) {
        sg += __shfl_down_sync(0xFFFFFFFFu, sg, o);
        br += __shfl_down_sync(0xFFFFFFFFu, br, o);
    }
    __shared__ double reds[8], redb[8];
    if ((t & 31) == 0) { reds[t >> 5] = sg; redb[t >> 5] = br; }
    __syncthreads();
    if (t == 0) {
        double ts = 0.0, tb = 0.0;
        #pragma unroll
        for (int j = 0; j < 8; j++) { ts += reds[j]; tb += redb[j]; }
        atomicAdd(&g_acc[2], ts);
        atomicAdd(&g_acc[1], tb);
        __threadfence();
        int tk = atomicAdd(&g_tick, 1);
        if (tk == 63) {
            double a0 = atomicAdd(&g_acc[0], 0.0);
            double a1 = atomicAdd(&g_acc[1], 0.0);
            double a2 = atomicAdd(&g_acc[2], 0.0);
            // total = act + lamb_reg*br + lamb * 4 * sum(g^2)
            out[0] = (float)(a0 + 0.0002 * a1 + 0.2 * a2);
        }
    }
}

// ---------------- launch ---------------------------------------------------
extern "C" void kernel_launch(void* const* d_in, const int* in_sizes, int n_in,
                              void* d_out, int out_size) {
    (void)in_sizes; (void)n_in; (void)out_size;
    const float* W  = (const float*)d_in[0];
    const float* Sg = (const float*)d_in[1];
    const float* Q  = (const float*)d_in[2];
    const float* s  = (const float*)d_in[3];
    const float* T  = (const float*)d_in[4];

    static bool attr_set = false;
    if (!attr_set) {
        cudaFuncSetAttribute(gemm_kernel, cudaFuncAttributeMaxDynamicSharedMemorySize, SMEM_BYTES);
        attr_set = true;
    }

    prep_kernel<<<1024, 256>>>((const float4*)W, (const float4*)Q, s, (const float4*)T,
                               (const float4*)Sg);
    gemm_kernel<<<NCTAS, 256, SMEM_BYTES>>>(W);
    sq_kernel<<<64, 256>>>((float*)d_out);
}